// round 11
// baseline (speedup 1.0000x reference)
#include <cuda_runtime.h>
#include <cstdint>
#include <math.h>

#define BB   2
#define SS   2048
#define DD   1024
#define HH   16
#define DKK  64
#define DFFN 4096
#define NTOK (BB*SS)

// ---------------- persistent scratch (no runtime allocation) ----------------
__device__ float g_xn [NTOK*DD];
__device__ float g_q  [NTOK*DD];
__device__ float g_k  [NTOK*DD];
__device__ float g_vT [(size_t)BB*DD*SS];      // V transposed: [b, d, s]
__device__ float g_ctx[NTOK*DD];
__device__ float g_x1 [NTOK*DD];
__device__ float g_h  [NTOK*DFFN];
__device__ float g_wqkvT[(size_t)3*DD*DD];     // [3072][1024] rows: q, k, v
__device__ float g_woT[DD*DD];
__device__ float g_w1T[(size_t)DFFN*DD];
__device__ float g_w2T[(size_t)DD*DFFN];

// ---------------- helpers ----------------
__device__ __forceinline__ float tf32r(float x){
    uint32_t u; asm("cvt.rna.tf32.f32 %0, %1;" : "=r"(u) : "f"(x));
    return __uint_as_float(u);
}
__device__ __forceinline__ uint32_t smem_u32(const void* p){
    uint32_t a;
    asm("{ .reg .u64 t; cvta.to.shared.u64 t, %1; cvt.u32.u64 %0, t; }" : "=r"(a) : "l"(p));
    return a;
}
__device__ __forceinline__ void cp16(uint32_t dst, const float* src){
    asm volatile("cp.async.cg.shared.global [%0], [%1], 16;"
                 :: "r"(dst), "l"(__cvta_generic_to_global(src)) : "memory");
}
__device__ __forceinline__ void mma8(float* acc, const uint32_t* af, uint32_t b0, uint32_t b1){
    asm volatile(
        "mma.sync.aligned.m16n8k8.row.col.f32.tf32.tf32.f32 "
        "{%0,%1,%2,%3}, {%4,%5,%6,%7}, {%8,%9}, {%0,%1,%2,%3};"
        : "+f"(acc[0]), "+f"(acc[1]), "+f"(acc[2]), "+f"(acc[3])
        : "r"(af[0]), "r"(af[1]), "r"(af[2]), "r"(af[3]), "r"(b0), "r"(b1));
}

// ---------------- LayerNorm (ddof=1, /(std+eps)); output tf32-rounded ----------------
__global__ __launch_bounds__(256) void ln_kernel(
    const float* __restrict__ x, float* __restrict__ out,
    const float* __restrict__ g, const float* __restrict__ b)
{
    __shared__ float red[256];
    int row = blockIdx.x;
    int tid = threadIdx.x;
    const float* xr = x + (size_t)row * DD;

    float v[4]; float s = 0.f;
#pragma unroll
    for (int i = 0; i < 4; i++) { v[i] = xr[tid + i*256]; s += v[i]; }
    red[tid] = s; __syncthreads();
    for (int o = 128; o > 0; o >>= 1) { if (tid < o) red[tid] += red[tid+o]; __syncthreads(); }
    float mean = red[0] / (float)DD;
    __syncthreads();

    float vs = 0.f;
#pragma unroll
    for (int i = 0; i < 4; i++) { float d = v[i] - mean; vs += d*d; }
    red[tid] = vs; __syncthreads();
    for (int o = 128; o > 0; o >>= 1) { if (tid < o) red[tid] += red[tid+o]; __syncthreads(); }
    float var = red[0] / (float)(DD - 1);
    float inv = 1.f / (sqrtf(var) + 1e-6f);
    float g0 = g[0], b0 = b[0];
    float* orow = out + (size_t)row * DD;
#pragma unroll
    for (int i = 0; i < 4; i++)
        orow[tid + i*256] = tf32r(g0 * (v[i] - mean) * inv + b0);
}

// ---------------- weight transpose (tf32-rounded) ----------------
__global__ __launch_bounds__(256) void transpose_kernel(
    const float* __restrict__ in, float* __restrict__ out, int R, int Cc)
{
    __shared__ float t[32][33];
    int c0 = blockIdx.x * 32, r0 = blockIdx.y * 32;
    int x = threadIdx.x, y = threadIdx.y;      // block (32, 8)
#pragma unroll
    for (int i = y; i < 32; i += 8) t[i][x] = in[(size_t)(r0 + i) * Cc + c0 + x];
    __syncthreads();
#pragma unroll
    for (int i = y; i < 32; i += 8) out[(size_t)(c0 + i) * R + r0 + x] = tf32r(t[x][i]);
}

// ============================================================
// Fused flash attention (tf32 mma.sync), per CTA: 128 query rows of one (b,h).
// ============================================================
#define SQ_STRIDE 68
#define SV_STRIDE 132
static constexpr int FLASH_SMEM =
    (128*SQ_STRIDE + 128*SQ_STRIDE + 64*SV_STRIDE + 128*SV_STRIDE) * 4 + 128 * 4;

__global__ __launch_bounds__(256)
void flash_kernel(const float* __restrict__ q, const float* __restrict__ k,
                  const float* __restrict__ vT, const int* __restrict__ msk,
                  float* __restrict__ ctx)
{
    extern __shared__ float sm[];
    float* sQ = sm;                            // [128][68]
    float* sK = sQ + 128*SQ_STRIDE;            // [128][68]
    float* sV = sK + 128*SQ_STRIDE;            // [64][132]
    float* sP = sV + 64*SV_STRIDE;             // [128][132]
    int*   sM = (int*)(sP + 128*SV_STRIDE);    // [128]

    const int tid = threadIdx.x;
    const int z  = blockIdx.y, bz = z >> 4, hz = z & 15;
    const int s0 = blockIdx.x * 128;
    const int warp = tid >> 5, lane = tid & 31;
    const int g = lane >> 2, qd = lane & 3;
    const int rowA = warp * 16;

    const float* qb = q  + ((size_t)(bz*SS + s0))*DD + hz*64;
    const float* kb = k  + ((size_t)bz*SS)*DD + hz*64;
    const float* vb = vT + (size_t)bz*DD*SS + (size_t)hz*64*SS;

    const uint32_t sQa = smem_u32(sQ), sKa = smem_u32(sK), sVa = smem_u32(sV);

#pragma unroll
    for (int p = 0; p < 8; p++){
        int slot = tid + p*256;
        int r = slot >> 4, c4 = slot & 15;
        cp16(sQa + (uint32_t)(r*SQ_STRIDE + c4*4)*4, qb + (size_t)r*DD + c4*4);
    }
    asm volatile("cp.async.commit_group;" ::: "memory");

    float m0 = -INFINITY, m1 = -INFINITY, l0 = 0.f, l1 = 0.f;
    float o[8][4];
#pragma unroll
    for (int nt = 0; nt < 8; nt++)
#pragma unroll
        for (int e = 0; e < 4; e++) o[nt][e] = 0.f;

    for (int kt = 0; kt < 16; kt++){
        __syncthreads();
#pragma unroll
        for (int p = 0; p < 8; p++){
            int slot = tid + p*256;
            int r = slot >> 4, c4 = slot & 15;
            cp16(sKa + (uint32_t)(r*SQ_STRIDE + c4*4)*4,
                 kb + (size_t)(kt*128 + r)*DD + c4*4);
        }
#pragma unroll
        for (int p = 0; p < 8; p++){
            int slot = tid + p*256;
            int r = slot >> 5, c4 = slot & 31;
            cp16(sVa + (uint32_t)(r*SV_STRIDE + c4*4)*4,
                 vb + (size_t)r*SS + kt*128 + c4*4);
        }
        asm volatile("cp.async.commit_group;" ::: "memory");
        if (tid < 128) sM[tid] = msk[bz*SS + kt*128 + tid];
        asm volatile("cp.async.wait_group 0;" ::: "memory");
        __syncthreads();

        float s[16][4];
#pragma unroll
        for (int nt = 0; nt < 16; nt++)
#pragma unroll
            for (int e = 0; e < 4; e++) s[nt][e] = 0.f;

#pragma unroll
        for (int ks = 0; ks < 64; ks += 8){
            uint32_t af[4];
            const uint32_t* ap  = (const uint32_t*)(sQ + (rowA + g    )*SQ_STRIDE + ks + qd);
            const uint32_t* ap8 = (const uint32_t*)(sQ + (rowA + g + 8)*SQ_STRIDE + ks + qd);
            af[0] = ap[0];  af[2] = ap[4];
            af[1] = ap8[0]; af[3] = ap8[4];
#pragma unroll
            for (int nt = 0; nt < 16; nt++){
                const uint32_t* bp = (const uint32_t*)(sK + (nt*8 + g)*SQ_STRIDE + ks + qd);
                mma8(s[nt], af, bp[0], bp[4]);
            }
        }

        float tm0 = -INFINITY, tm1 = -INFINITY;
#pragma unroll
        for (int nt = 0; nt < 16; nt++){
            int mc0 = sM[nt*8 + 2*qd], mc1 = sM[nt*8 + 2*qd + 1];
            s[nt][0] = mc0 ? s[nt][0] * 0.125f : -1.0f;
            s[nt][1] = mc1 ? s[nt][1] * 0.125f : -1.0f;
            s[nt][2] = mc0 ? s[nt][2] * 0.125f : -1.0f;
            s[nt][3] = mc1 ? s[nt][3] * 0.125f : -1.0f;
            tm0 = fmaxf(tm0, fmaxf(s[nt][0], s[nt][1]));
            tm1 = fmaxf(tm1, fmaxf(s[nt][2], s[nt][3]));
        }
        tm0 = fmaxf(tm0, __shfl_xor_sync(0xffffffffu, tm0, 1));
        tm0 = fmaxf(tm0, __shfl_xor_sync(0xffffffffu, tm0, 2));
        tm1 = fmaxf(tm1, __shfl_xor_sync(0xffffffffu, tm1, 1));
        tm1 = fmaxf(tm1, __shfl_xor_sync(0xffffffffu, tm1, 2));

        float mn0 = fmaxf(m0, tm0), mn1 = fmaxf(m1, tm1);
        float a0 = __expf(m0 - mn0), a1 = __expf(m1 - mn1);

        float ts0 = 0.f, ts1 = 0.f;
        float* pr0 = sP + (rowA + g    )*SV_STRIDE + 2*qd;
        float* pr1 = sP + (rowA + g + 8)*SV_STRIDE + 2*qd;
#pragma unroll
        for (int nt = 0; nt < 16; nt++){
            float p0 = __expf(s[nt][0] - mn0), p1 = __expf(s[nt][1] - mn0);
            float p2 = __expf(s[nt][2] - mn1), p3 = __expf(s[nt][3] - mn1);
            ts0 += p0 + p1; ts1 += p2 + p3;
            *(float2*)(pr0 + nt*8) = make_float2(tf32r(p0), tf32r(p1));
            *(float2*)(pr1 + nt*8) = make_float2(tf32r(p2), tf32r(p3));
        }
        ts0 += __shfl_xor_sync(0xffffffffu, ts0, 1);
        ts0 += __shfl_xor_sync(0xffffffffu, ts0, 2);
        ts1 += __shfl_xor_sync(0xffffffffu, ts1, 1);
        ts1 += __shfl_xor_sync(0xffffffffu, ts1, 2);

        l0 = l0 * a0 + ts0;  l1 = l1 * a1 + ts1;
        m0 = mn0;  m1 = mn1;

#pragma unroll
        for (int nt = 0; nt < 8; nt++){
            o[nt][0] *= a0; o[nt][1] *= a0;
            o[nt][2] *= a1; o[nt][3] *= a1;
        }
        __syncwarp();

#pragma unroll
        for (int kk = 0; kk < 128; kk += 8){
            uint32_t af[4];
            const uint32_t* ap  = (const uint32_t*)(sP + (rowA + g    )*SV_STRIDE + kk + qd);
            const uint32_t* ap8 = (const uint32_t*)(sP + (rowA + g + 8)*SV_STRIDE + kk + qd);
            af[0] = ap[0];  af[2] = ap[4];
            af[1] = ap8[0]; af[3] = ap8[4];
#pragma unroll
            for (int nt = 0; nt < 8; nt++){
                const uint32_t* bp = (const uint32_t*)(sV + (nt*8 + g)*SV_STRIDE + kk + qd);
                mma8(o[nt], af, bp[0], bp[4]);
            }
        }
    }

    float i0 = 1.f / l0, i1 = 1.f / l1;
    size_t r0i = ((size_t)(bz*SS + s0 + rowA + g    ))*DD + hz*64;
    size_t r1i = ((size_t)(bz*SS + s0 + rowA + g + 8))*DD + hz*64;
#pragma unroll
    for (int nt = 0; nt < 8; nt++){
        int c = nt*8 + 2*qd;
        ctx[r0i + c]     = tf32r(o[nt][0] * i0);
        ctx[r0i + c + 1] = tf32r(o[nt][1] * i0);
        ctx[r1i + c]     = tf32r(o[nt][2] * i1);
        ctx[r1i + c + 1] = tf32r(o[nt][3] * i1);
    }
}

// ============================================================
// tf32 mma.sync GEMM: CTA tile 128 x BN, warp tile (MT*16) x (NT*8).
// qkv mode: B = wqkvT [3072 x 1024]; output routed by column segment
//   seg0 -> Cq (normal), seg1 -> Ck (normal), seg2 -> Cv (transposed [b,d,s]).
// ============================================================
template<int BN, int WGX, int MT, int NT>
__global__ __launch_bounds__(256)
void mma_gemm(const float* __restrict__ A, const float* __restrict__ Bt,
              float* __restrict__ C, float* __restrict__ Ck, float* __restrict__ Cv,
              const float* __restrict__ bias, const float* __restrict__ biasK,
              const float* __restrict__ biasV,
              const float* __restrict__ resid,
              int K, int lda, int ldb, int ldc,
              float alpha, int relu, int storeT, int roundOut, int qkv)
{
    extern __shared__ float sm[];
    constexpr int ASZ = 128 * 36;
    constexpr int BSZ = BN * 36;
    float* A0 = sm;
    float* B0 = sm + 2 * ASZ;

    const int tid = threadIdx.x;
    const int rowStart = blockIdx.y * 128;
    const int colStart = blockIdx.x * BN;      // column into B rows

    // output routing
    float* Cb = C;
    const float* biasP = bias;
    int cCol = colStart;
    int doT  = storeT;
    if (qkv){
        int seg = colStart >> 10;
        cCol = colStart & 1023;
        if (seg == 1)      { Cb = Ck; biasP = biasK; }
        else if (seg == 2) { Cb = Cv; biasP = biasV; doT = 1; }
    }

    const uint32_t aBase = smem_u32(A0), bBase = smem_u32(B0);

    auto loadA = [&](int buf, int k0){
        uint32_t dst = aBase + (uint32_t)buf * (ASZ * 4);
#pragma unroll
        for (int p = 0; p < 4; p++){
            int slot = tid + p * 256;
            int r = slot >> 3, qq = slot & 7;
            cp16(dst + (uint32_t)(r * 36 + qq * 4) * 4,
                 A + (size_t)(rowStart + r) * lda + k0 + qq * 4);
        }
    };
    auto loadB = [&](int buf, int k0){
        uint32_t dst = bBase + (uint32_t)buf * (BSZ * 4);
#pragma unroll
        for (int p = 0; p < BN / 32; p++){
            int slot = tid + p * 256;
            int r = slot >> 3, qq = slot & 7;
            cp16(dst + (uint32_t)(r * 36 + qq * 4) * 4,
                 Bt + (size_t)(colStart + r) * ldb + k0 + qq * 4);
        }
    };

    const int warp = tid >> 5, lane = tid & 31;
    const int g = lane >> 2, qd = lane & 3;
    const int wy = warp / WGX, wx = warp % WGX;
    const int m0 = wy * MT * 16, n0 = wx * NT * 8;

    float acc[MT][NT][4];
#pragma unroll
    for (int mt = 0; mt < MT; mt++)
#pragma unroll
        for (int nt = 0; nt < NT; nt++)
#pragma unroll
            for (int e = 0; e < 4; e++) acc[mt][nt][e] = 0.f;

    const int nk = K >> 5;
    loadA(0, 0); loadB(0, 0);
    asm volatile("cp.async.commit_group;" ::: "memory");

    for (int s = 0; s < nk; s++){
        if (s + 1 < nk){ loadA((s + 1) & 1, (s + 1) * 32); loadB((s + 1) & 1, (s + 1) * 32); }
        asm volatile("cp.async.commit_group;" ::: "memory");
        asm volatile("cp.async.wait_group 1;" ::: "memory");
        __syncthreads();

        const float* As = A0 + (s & 1) * ASZ;
        const float* Bs = B0 + (s & 1) * BSZ;
#pragma unroll
        for (int ks = 0; ks < 32; ks += 8){
            uint32_t af[MT][4], bf[NT][2];
#pragma unroll
            for (int mt = 0; mt < MT; mt++){
                const uint32_t* ap  = (const uint32_t*)(As + (m0 + mt*16 + g    ) * 36 + ks + qd);
                const uint32_t* ap8 = (const uint32_t*)(As + (m0 + mt*16 + g + 8) * 36 + ks + qd);
                af[mt][0] = ap[0];  af[mt][2] = ap[4];
                af[mt][1] = ap8[0]; af[mt][3] = ap8[4];
            }
#pragma unroll
            for (int nt = 0; nt < NT; nt++){
                const uint32_t* bp = (const uint32_t*)(Bs + (n0 + nt*8 + g) * 36 + ks + qd);
                bf[nt][0] = bp[0]; bf[nt][1] = bp[4];
            }
#pragma unroll
            for (int mt = 0; mt < MT; mt++)
#pragma unroll
                for (int nt = 0; nt < NT; nt++)
                    mma8(acc[mt][nt], af[mt], bf[nt][0], bf[nt][1]);
        }
        __syncthreads();
    }

    // ---------------- epilogue ----------------
#pragma unroll
    for (int mt = 0; mt < MT; mt++)
#pragma unroll
        for (int nt = 0; nt < NT; nt++)
#pragma unroll
            for (int e = 0; e < 4; e++){
                int r = rowStart + m0 + mt * 16 + g + ((e >= 2) ? 8 : 0);
                int c = cCol + n0 + nt * 8 + qd * 2 + (e & 1);
                float v = alpha * acc[mt][nt][e];
                if (biasP) v += biasP[c];
                if (resid) v += resid[(size_t)r * ldc + c];
                if (relu)  v = fmaxf(v, 0.f);
                if (roundOut) v = tf32r(v);
                if (!doT) {
                    Cb[(size_t)r * ldc + c] = v;
                } else {
                    int bb = r >> 11;            // r / SS
                    int si = r & (SS - 1);
                    Cb[((size_t)bb * DD + c) * SS + si] = v;
                }
            }
}

// ---------------- host-side launcher ----------------
template<int BN, int WGX, int MT, int NT>
static void run_gemm(const float* A, const float* Bt,
                     float* C, float* Ck, float* Cv,
                     const float* bias, const float* biasK, const float* biasV,
                     const float* resid,
                     int M, int N, int K, int lda, int ldb, int ldc,
                     float alpha, int relu, int storeT, int roundOut, int qkv)
{
    constexpr int SMEM = (2 * 128 * 36 + 2 * BN * 36) * 4;
    cudaFuncSetAttribute(mma_gemm<BN, WGX, MT, NT>,
                         cudaFuncAttributeMaxDynamicSharedMemorySize, SMEM);
    dim3 grid(N / BN, M / 128, 1);
    mma_gemm<BN, WGX, MT, NT><<<grid, 256, SMEM>>>(
        A, Bt, C, Ck, Cv, bias, biasK, biasV, resid,
        K, lda, ldb, ldc, alpha, relu, storeT, roundOut, qkv);
}

extern "C" void kernel_launch(void* const* d_in, const int* in_sizes, int n_in,
                              void* d_out, int out_size)
{
    const float* x   = (const float*)d_in[0];
    const int*   msk = (const int*)  d_in[1];
    const float* wq  = (const float*)d_in[2];
    const float* bq  = (const float*)d_in[3];
    const float* wk  = (const float*)d_in[4];
    const float* bk  = (const float*)d_in[5];
    const float* wv  = (const float*)d_in[6];
    const float* bv  = (const float*)d_in[7];
    const float* wo  = (const float*)d_in[8];
    const float* bo  = (const float*)d_in[9];
    const float* w1  = (const float*)d_in[10];
    const float* b1  = (const float*)d_in[11];
    const float* w2  = (const float*)d_in[12];
    const float* b2  = (const float*)d_in[13];
    const float* g1  = (const float*)d_in[14];
    const float* be1 = (const float*)d_in[15];
    const float* g2  = (const float*)d_in[16];
    const float* be2 = (const float*)d_in[17];
    float* out = (float*)d_out;

    float *xn,*q,*k,*vT,*ctx,*x1,*hb,*wqkvT,*woT,*w1T,*w2T;
    cudaGetSymbolAddress((void**)&xn,    g_xn);
    cudaGetSymbolAddress((void**)&q,     g_q);
    cudaGetSymbolAddress((void**)&k,     g_k);
    cudaGetSymbolAddress((void**)&vT,    g_vT);
    cudaGetSymbolAddress((void**)&ctx,   g_ctx);
    cudaGetSymbolAddress((void**)&x1,    g_x1);
    cudaGetSymbolAddress((void**)&hb,    g_h);
    cudaGetSymbolAddress((void**)&wqkvT, g_wqkvT);
    cudaGetSymbolAddress((void**)&woT,   g_woT);
    cudaGetSymbolAddress((void**)&w1T,   g_w1T);
    cudaGetSymbolAddress((void**)&w2T,   g_w2T);

    dim3 tb(32, 8);
    transpose_kernel<<<dim3(DD/32,   DD/32),   tb>>>(wq, wqkvT,                    DD, DD);
    transpose_kernel<<<dim3(DD/32,   DD/32),   tb>>>(wk, wqkvT + (size_t)DD*DD,    DD, DD);
    transpose_kernel<<<dim3(DD/32,   DD/32),   tb>>>(wv, wqkvT + (size_t)2*DD*DD,  DD, DD);
    transpose_kernel<<<dim3(DD/32,   DD/32),   tb>>>(wo, woT, DD,   DD);
    transpose_kernel<<<dim3(DFFN/32, DD/32),   tb>>>(w1, w1T, DD,   DFFN);
    transpose_kernel<<<dim3(DD/32,   DFFN/32), tb>>>(w2, w2T, DFFN, DD);

    // 1) LN1 (tf32-rounded output)
    ln_kernel<<<NTOK, 256>>>(x, xn, g1, be1);

    // 2) fused QKV projection: N=3072 at BN=128 (proven tile config);
    //    seg0->q, seg1->k, seg2->vT [b,d,s]
    run_gemm<128,4,4,4>(xn, wqkvT, q, k, vT, bq, bk, bv, nullptr,
                        NTOK, 3*DD, DD, DD, DD, DD, 1.f, 0, 0, 1, 1);

    // 3) fused attention: QK^T/8 -> mask(-1) -> softmax -> @V
    {
        cudaFuncSetAttribute(flash_kernel, cudaFuncAttributeMaxDynamicSharedMemorySize,
                             FLASH_SMEM);
        dim3 grid(SS/128, BB*HH);
        flash_kernel<<<grid, 256, FLASH_SMEM>>>(q, k, vT, msk, ctx);
    }

    // 4) x1 = x + ctx @ wo + bo (fp32)
    run_gemm<128,4,4,4>(ctx, woT, x1, nullptr, nullptr, bo, nullptr, nullptr, x,
                        NTOK, DD, DD, DD, DD, DD, 1.f, 0, 0, 0, 0);

    // 5) LN2
    ln_kernel<<<NTOK, 256>>>(x1, xn, g2, be2);

    // 6) h = relu(xn @ w1 + b1) (tf32-rounded)
    run_gemm<128,4,4,4>(xn, w1T, hb, nullptr, nullptr, b1, nullptr, nullptr, nullptr,
                        NTOK, DFFN, DD, DD, DD, DFFN, 1.f, 1, 0, 1, 0);

    // 7) out = x1 + h @ w2 + b2 (fp32)
    run_gemm<128,4,4,4>(hb, w2T, out, nullptr, nullptr, b2, nullptr, nullptr, x1,
                        NTOK, DD, DFFN, DFFN, DFFN, DD, 1.f, 0, 0, 0, 0);
}

// round 12
// speedup vs baseline: 1.6812x; 1.6812x over previous
#include <cuda_runtime.h>
#include <cuda_fp16.h>
#include <cstdint>
#include <math.h>

#define BB   2
#define SS   2048
#define DD   1024
#define HH   16
#define DKK  64
#define DFFN 4096
#define NTOK (BB*SS)

// ---------------- persistent scratch (no runtime allocation) ----------------
__device__ __half g_xn [NTOK*DD];
__device__ __half g_q  [NTOK*DD];
__device__ __half g_k  [NTOK*DD];
__device__ __half g_vT [(size_t)BB*DD*SS];     // V transposed: [b, d, s]
__device__ __half g_ctx[NTOK*DD];
__device__ float  g_x1 [NTOK*DD];
__device__ __half g_h  [(size_t)NTOK*DFFN];
__device__ __half g_wqT[DD*DD];
__device__ __half g_wkT[DD*DD];
__device__ __half g_wvT[DD*DD];
__device__ __half g_woT[DD*DD];
__device__ __half g_w1T[(size_t)DFFN*DD];
__device__ __half g_w2T[(size_t)DD*DFFN];

// ---------------- helpers ----------------
__device__ __forceinline__ uint32_t smem_u32(const void* p){
    uint32_t a;
    asm("{ .reg .u64 t; cvta.to.shared.u64 t, %1; cvt.u32.u64 %0, t; }" : "=r"(a) : "l"(p));
    return a;
}
__device__ __forceinline__ void cp16(uint32_t dst, const void* src){
    asm volatile("cp.async.cg.shared.global [%0], [%1], 16;"
                 :: "r"(dst), "l"(__cvta_generic_to_global(src)) : "memory");
}
__device__ __forceinline__ void mma16(float* acc, const uint32_t* af, uint32_t b0, uint32_t b1){
    asm volatile(
        "mma.sync.aligned.m16n8k16.row.col.f32.f16.f16.f32 "
        "{%0,%1,%2,%3}, {%4,%5,%6,%7}, {%8,%9}, {%0,%1,%2,%3};"
        : "+f"(acc[0]), "+f"(acc[1]), "+f"(acc[2]), "+f"(acc[3])
        : "r"(af[0]), "r"(af[1]), "r"(af[2]), "r"(af[3]), "r"(b0), "r"(b1));
}

// ---------------- LayerNorm (ddof=1, /(std+eps)); output half ----------------
__global__ __launch_bounds__(256) void ln_kernel(
    const float* __restrict__ x, __half* __restrict__ out,
    const float* __restrict__ g, const float* __restrict__ b)
{
    __shared__ float red[256];
    int row = blockIdx.x;
    int tid = threadIdx.x;
    const float* xr = x + (size_t)row * DD;

    float v[4]; float s = 0.f;
#pragma unroll
    for (int i = 0; i < 4; i++) { v[i] = xr[tid + i*256]; s += v[i]; }
    red[tid] = s; __syncthreads();
    for (int o = 128; o > 0; o >>= 1) { if (tid < o) red[tid] += red[tid+o]; __syncthreads(); }
    float mean = red[0] / (float)DD;
    __syncthreads();

    float vs = 0.f;
#pragma unroll
    for (int i = 0; i < 4; i++) { float d = v[i] - mean; vs += d*d; }
    red[tid] = vs; __syncthreads();
    for (int o = 128; o > 0; o >>= 1) { if (tid < o) red[tid] += red[tid+o]; __syncthreads(); }
    float var = red[0] / (float)(DD - 1);
    float inv = 1.f / (sqrtf(var) + 1e-6f);
    float g0 = g[0], b0 = b[0];
    __half* orow = out + (size_t)row * DD;
#pragma unroll
    for (int i = 0; i < 4; i++)
        orow[tid + i*256] = __float2half(g0 * (v[i] - mean) * inv + b0);
}

// ---------------- weight transpose: float in -> half out [C][R] ----------------
__global__ __launch_bounds__(256) void transpose_kernel(
    const float* __restrict__ in, __half* __restrict__ out, int R, int Cc)
{
    __shared__ float t[32][33];
    int c0 = blockIdx.x * 32, r0 = blockIdx.y * 32;
    int x = threadIdx.x, y = threadIdx.y;      // block (32, 8)
#pragma unroll
    for (int i = y; i < 32; i += 8) t[i][x] = in[(size_t)(r0 + i) * Cc + c0 + x];
    __syncthreads();
#pragma unroll
    for (int i = y; i < 32; i += 8) out[(size_t)(c0 + i) * R + r0 + x] = __float2half(t[x][i]);
}

// ============================================================
// Fused flash attention (fp16 mma.sync m16n8k16), per CTA: 128 query rows, one (b,h).
// K-tiles of 128 keys; online softmax in f32; scores=(q.k)/8; mask==0 -> -1.0.
// smem u32 layout: sQ [128][36], sK [128][36], sV [64][68], sP [128][68], sM[128]
// ============================================================
static constexpr int FQ = 0;
static constexpr int FK = 128*36;
static constexpr int FV = FK + 128*36;          // 9216
static constexpr int FP = FV + 64*68;           // 13568
static constexpr int FM = FP + 128*68;          // 22272
static constexpr int FLASH_SMEM = (FM + 128) * 4;   // 89600 B

__global__ __launch_bounds__(256)
void flash_kernel(const __half* __restrict__ q, const __half* __restrict__ k,
                  const __half* __restrict__ vT, const int* __restrict__ msk,
                  __half* __restrict__ ctx)
{
    extern __shared__ uint32_t sm32[];
    int* sM = (int*)(sm32 + FM);

    const int tid = threadIdx.x;
    const int z  = blockIdx.y, bz = z >> 4, hz = z & 15;
    const int s0 = blockIdx.x * 128;
    const int warp = tid >> 5, lane = tid & 31;
    const int g = lane >> 2, qd = lane & 3;
    const int rowA = warp * 16;

    const __half* qb = q  + ((size_t)(bz*SS + s0))*DD + hz*64;
    const __half* kb = k  + ((size_t)bz*SS)*DD + hz*64;
    const __half* vb = vT + (size_t)bz*DD*SS + (size_t)hz*64*SS;

    const uint32_t base = smem_u32(sm32);

    // Q tile (once): 128 rows x 64 halves (128B) = 8 chunks/row
#pragma unroll
    for (int p = 0; p < 4; p++){
        int slot = tid + p*256;
        int r = slot >> 3, qq = slot & 7;
        cp16(base + (uint32_t)(FQ + r*36 + qq*4)*4, qb + (size_t)r*DD + qq*8);
    }
    asm volatile("cp.async.commit_group;" ::: "memory");

    float m0 = -INFINITY, m1 = -INFINITY, l0 = 0.f, l1 = 0.f;
    float o[8][4];
#pragma unroll
    for (int nt = 0; nt < 8; nt++)
#pragma unroll
        for (int e = 0; e < 4; e++) o[nt][e] = 0.f;

    for (int kt = 0; kt < 16; kt++){
        __syncthreads();                       // previous tile fully consumed
        // K tile: [key 128][dk 64 halves]
#pragma unroll
        for (int p = 0; p < 4; p++){
            int slot = tid + p*256;
            int r = slot >> 3, qq = slot & 7;
            cp16(base + (uint32_t)(FK + r*36 + qq*4)*4,
                 kb + (size_t)(kt*128 + r)*DD + qq*8);
        }
        // V tile from vT: [dk 64][key 128 halves] (256B rows = 16 chunks)
#pragma unroll
        for (int p = 0; p < 4; p++){
            int slot = tid + p*256;
            int r = slot >> 4, qq = slot & 15;
            cp16(base + (uint32_t)(FV + r*68 + qq*4)*4,
                 vb + (size_t)r*SS + kt*128 + qq*8);
        }
        asm volatile("cp.async.commit_group;" ::: "memory");
        if (tid < 128) sM[tid] = msk[bz*SS + kt*128 + tid];
        asm volatile("cp.async.wait_group 0;" ::: "memory");
        __syncthreads();

        // ---- scores: 16 rows x 128 keys per warp, dk=64 -> 4 k16 chunks ----
        float s[16][4];
#pragma unroll
        for (int nt = 0; nt < 16; nt++)
#pragma unroll
            for (int e = 0; e < 4; e++) s[nt][e] = 0.f;

#pragma unroll
        for (int ks = 0; ks < 32; ks += 8){    // u32 offset per k16 chunk
            uint32_t af[4];
            af[0] = sm32[FQ + (rowA + g    )*36 + ks + qd];
            af[1] = sm32[FQ + (rowA + g + 8)*36 + ks + qd];
            af[2] = sm32[FQ + (rowA + g    )*36 + ks + qd + 4];
            af[3] = sm32[FQ + (rowA + g + 8)*36 + ks + qd + 4];
#pragma unroll
            for (int nt = 0; nt < 16; nt++){
                uint32_t b0 = sm32[FK + (nt*8 + g)*36 + ks + qd];
                uint32_t b1 = sm32[FK + (nt*8 + g)*36 + ks + qd + 4];
                mma16(s[nt], af, b0, b1);
            }
        }

        // ---- scale + mask + tile max ----
        float tm0 = -INFINITY, tm1 = -INFINITY;
#pragma unroll
        for (int nt = 0; nt < 16; nt++){
            int mc0 = sM[nt*8 + 2*qd], mc1 = sM[nt*8 + 2*qd + 1];
            s[nt][0] = mc0 ? s[nt][0] * 0.125f : -1.0f;
            s[nt][1] = mc1 ? s[nt][1] * 0.125f : -1.0f;
            s[nt][2] = mc0 ? s[nt][2] * 0.125f : -1.0f;
            s[nt][3] = mc1 ? s[nt][3] * 0.125f : -1.0f;
            tm0 = fmaxf(tm0, fmaxf(s[nt][0], s[nt][1]));
            tm1 = fmaxf(tm1, fmaxf(s[nt][2], s[nt][3]));
        }
        tm0 = fmaxf(tm0, __shfl_xor_sync(0xffffffffu, tm0, 1));
        tm0 = fmaxf(tm0, __shfl_xor_sync(0xffffffffu, tm0, 2));
        tm1 = fmaxf(tm1, __shfl_xor_sync(0xffffffffu, tm1, 1));
        tm1 = fmaxf(tm1, __shfl_xor_sync(0xffffffffu, tm1, 2));

        float mn0 = fmaxf(m0, tm0), mn1 = fmaxf(m1, tm1);
        float a0 = __expf(m0 - mn0), a1 = __expf(m1 - mn1);

        // ---- exp, row sums, write P (half2) to smem ----
        float ts0 = 0.f, ts1 = 0.f;
        uint32_t pr0 = FP + (rowA + g    )*68 + qd;
        uint32_t pr1 = FP + (rowA + g + 8)*68 + qd;
#pragma unroll
        for (int nt = 0; nt < 16; nt++){
            float p0 = __expf(s[nt][0] - mn0), p1 = __expf(s[nt][1] - mn0);
            float p2 = __expf(s[nt][2] - mn1), p3 = __expf(s[nt][3] - mn1);
            ts0 += p0 + p1; ts1 += p2 + p3;
            *reinterpret_cast<__half2*>(&sm32[pr0 + nt*4]) = __floats2half2_rn(p0, p1);
            *reinterpret_cast<__half2*>(&sm32[pr1 + nt*4]) = __floats2half2_rn(p2, p3);
        }
        ts0 += __shfl_xor_sync(0xffffffffu, ts0, 1);
        ts0 += __shfl_xor_sync(0xffffffffu, ts0, 2);
        ts1 += __shfl_xor_sync(0xffffffffu, ts1, 1);
        ts1 += __shfl_xor_sync(0xffffffffu, ts1, 2);

        l0 = l0 * a0 + ts0;  l1 = l1 * a1 + ts1;
        m0 = mn0;  m1 = mn1;

#pragma unroll
        for (int nt = 0; nt < 8; nt++){
            o[nt][0] *= a0; o[nt][1] *= a0;
            o[nt][2] *= a1; o[nt][3] *= a1;
        }
        __syncwarp();

        // ---- P @ V : 128 keys -> 8 k16 chunks ----
#pragma unroll
        for (int kk = 0; kk < 64; kk += 8){    // u32 offset
            uint32_t af[4];
            af[0] = sm32[FP + (rowA + g    )*68 + kk + qd];
            af[1] = sm32[FP + (rowA + g + 8)*68 + kk + qd];
            af[2] = sm32[FP + (rowA + g    )*68 + kk + qd + 4];
            af[3] = sm32[FP + (rowA + g + 8)*68 + kk + qd + 4];
#pragma unroll
            for (int nt = 0; nt < 8; nt++){
                uint32_t b0 = sm32[FV + (nt*8 + g)*68 + kk + qd];
                uint32_t b1 = sm32[FV + (nt*8 + g)*68 + kk + qd + 4];
                mma16(o[nt], af, b0, b1);
            }
        }
    }

    // ---- epilogue: normalize, write ctx [B,S,H,DK] as half ----
    float i0 = 1.f / l0, i1 = 1.f / l1;
    size_t r0i = ((size_t)(bz*SS + s0 + rowA + g    ))*DD + hz*64;
    size_t r1i = ((size_t)(bz*SS + s0 + rowA + g + 8))*DD + hz*64;
#pragma unroll
    for (int nt = 0; nt < 8; nt++){
        int c = nt*8 + 2*qd;
        *reinterpret_cast<__half2*>(&ctx[r0i + c]) = __floats2half2_rn(o[nt][0]*i0, o[nt][1]*i0);
        *reinterpret_cast<__half2*>(&ctx[r1i + c]) = __floats2half2_rn(o[nt][2]*i1, o[nt][3]*i1);
    }
}

// ============================================================
// fp16 mma.sync GEMM: C[128 x 128] per CTA = A @ Bt^T (+bias)(+resid)(relu)
// A: [M,K] half row-major. Bt: [N,K] half row-major. K % 64 == 0.
// Stage = 64 halves of K; double-buffered cp.async; warp tile 64x32.
// Output: half (outHalf/storeT) or float (+resid).
// ============================================================
static constexpr int HG_ASZ = 128 * 36;     // u32 per stage (A and B identical)
static constexpr int HG_SMEM = 4 * HG_ASZ * 4;   // 73728 B

__global__ __launch_bounds__(256)
void hgemm(const __half* __restrict__ A, const __half* __restrict__ Bt,
           float* __restrict__ Cf, __half* __restrict__ Ch,
           const float* __restrict__ bias, const float* __restrict__ resid,
           int K, int lda, int ldb, int ldc,
           int relu, int storeT, int outHalf)
{
    extern __shared__ uint32_t sm32[];
    uint32_t* A0 = sm32;
    uint32_t* B0 = sm32 + 2 * HG_ASZ;

    const int tid = threadIdx.x;
    const int rowStart = blockIdx.y * 128;
    const int colStart = blockIdx.x * 128;

    const uint32_t aBase = smem_u32(A0), bBase = smem_u32(B0);

    auto loadA = [&](int buf, int k0){
        uint32_t dst = aBase + (uint32_t)buf * (HG_ASZ * 4);
#pragma unroll
        for (int p = 0; p < 4; p++){
            int slot = tid + p * 256;
            int r = slot >> 3, qq = slot & 7;
            cp16(dst + (uint32_t)(r * 36 + qq * 4) * 4,
                 A + (size_t)(rowStart + r) * lda + k0 + qq * 8);
        }
    };
    auto loadB = [&](int buf, int k0){
        uint32_t dst = bBase + (uint32_t)buf * (HG_ASZ * 4);
#pragma unroll
        for (int p = 0; p < 4; p++){
            int slot = tid + p * 256;
            int r = slot >> 3, qq = slot & 7;
            cp16(dst + (uint32_t)(r * 36 + qq * 4) * 4,
                 Bt + (size_t)(colStart + r) * ldb + k0 + qq * 8);
        }
    };

    const int warp = tid >> 5, lane = tid & 31;
    const int g = lane >> 2, qd = lane & 3;
    const int wy = warp >> 2, wx = warp & 3;
    const int m0 = wy * 64, n0 = wx * 32;

    float acc[4][4][4];
#pragma unroll
    for (int mt = 0; mt < 4; mt++)
#pragma unroll
        for (int nt = 0; nt < 4; nt++)
#pragma unroll
            for (int e = 0; e < 4; e++) acc[mt][nt][e] = 0.f;

    const int nk = K >> 6;                     // 64 halves per stage
    loadA(0, 0); loadB(0, 0);
    asm volatile("cp.async.commit_group;" ::: "memory");

    for (int s = 0; s < nk; s++){
        if (s + 1 < nk){ loadA((s + 1) & 1, (s + 1) * 64); loadB((s + 1) & 1, (s + 1) * 64); }
        asm volatile("cp.async.commit_group;" ::: "memory");
        asm volatile("cp.async.wait_group 1;" ::: "memory");
        __syncthreads();

        const uint32_t* As = A0 + (s & 1) * HG_ASZ;
        const uint32_t* Bs = B0 + (s & 1) * HG_ASZ;
#pragma unroll
        for (int ks = 0; ks < 32; ks += 8){    // 4 chunks of k16 (u32 offsets)
            uint32_t af[4][4], bf[4][2];
#pragma unroll
            for (int mt = 0; mt < 4; mt++){
                const uint32_t* ap  = As + (m0 + mt*16 + g    ) * 36 + ks + qd;
                const uint32_t* ap8 = As + (m0 + mt*16 + g + 8) * 36 + ks + qd;
                af[mt][0] = ap[0];  af[mt][1] = ap8[0];
                af[mt][2] = ap[4];  af[mt][3] = ap8[4];
            }
#pragma unroll
            for (int nt = 0; nt < 4; nt++){
                const uint32_t* bp = Bs + (n0 + nt*8 + g) * 36 + ks + qd;
                bf[nt][0] = bp[0]; bf[nt][1] = bp[4];
            }
#pragma unroll
            for (int mt = 0; mt < 4; mt++)
#pragma unroll
                for (int nt = 0; nt < 4; nt++)
                    mma16(acc[mt][nt], af[mt], bf[nt][0], bf[nt][1]);
        }
        __syncthreads();
    }

    // ---------------- epilogue ----------------
#pragma unroll
    for (int mt = 0; mt < 4; mt++)
#pragma unroll
        for (int nt = 0; nt < 4; nt++)
#pragma unroll
            for (int e = 0; e < 4; e++){
                int r = rowStart + m0 + mt * 16 + g + ((e >= 2) ? 8 : 0);
                int c = colStart + n0 + nt * 8 + qd * 2 + (e & 1);
                float v = acc[mt][nt][e];
                if (bias)  v += bias[c];
                if (resid) v += resid[(size_t)r * ldc + c];
                if (relu)  v = fmaxf(v, 0.f);
                if (storeT) {
                    int bb = r >> 11;          // r / SS
                    int si = r & (SS - 1);
                    Ch[((size_t)bb * DD + c) * SS + si] = __float2half(v);
                } else if (outHalf) {
                    Ch[(size_t)r * ldc + c] = __float2half(v);
                } else {
                    Cf[(size_t)r * ldc + c] = v;
                }
            }
}

// ---------------- host-side launcher ----------------
static void run_hgemm(const __half* A, const __half* Bt,
                      float* Cf, __half* Ch,
                      const float* bias, const float* resid,
                      int M, int N, int K, int lda, int ldb, int ldc,
                      int relu, int storeT, int outHalf)
{
    cudaFuncSetAttribute(hgemm, cudaFuncAttributeMaxDynamicSharedMemorySize, HG_SMEM);
    dim3 grid(N / 128, M / 128, 1);
    hgemm<<<grid, 256, HG_SMEM>>>(A, Bt, Cf, Ch, bias, resid,
                                  K, lda, ldb, ldc, relu, storeT, outHalf);
}

extern "C" void kernel_launch(void* const* d_in, const int* in_sizes, int n_in,
                              void* d_out, int out_size)
{
    const float* x   = (const float*)d_in[0];
    const int*   msk = (const int*)  d_in[1];
    const float* wq  = (const float*)d_in[2];
    const float* bq  = (const float*)d_in[3];
    const float* wk  = (const float*)d_in[4];
    const float* bk  = (const float*)d_in[5];
    const float* wv  = (const float*)d_in[6];
    const float* bv  = (const float*)d_in[7];
    const float* wo  = (const float*)d_in[8];
    const float* bo  = (const float*)d_in[9];
    const float* w1  = (const float*)d_in[10];
    const float* b1  = (const float*)d_in[11];
    const float* w2  = (const float*)d_in[12];
    const float* b2  = (const float*)d_in[13];
    const float* g1  = (const float*)d_in[14];
    const float* be1 = (const float*)d_in[15];
    const float* g2  = (const float*)d_in[16];
    const float* be2 = (const float*)d_in[17];
    float* out = (float*)d_out;

    __half *xn,*q,*k,*vT,*ctx,*hb,*wqT,*wkT,*wvT,*woT,*w1T,*w2T;
    float *x1;
    cudaGetSymbolAddress((void**)&xn,  g_xn);
    cudaGetSymbolAddress((void**)&q,   g_q);
    cudaGetSymbolAddress((void**)&k,   g_k);
    cudaGetSymbolAddress((void**)&vT,  g_vT);
    cudaGetSymbolAddress((void**)&ctx, g_ctx);
    cudaGetSymbolAddress((void**)&x1,  g_x1);
    cudaGetSymbolAddress((void**)&hb,  g_h);
    cudaGetSymbolAddress((void**)&wqT, g_wqT);
    cudaGetSymbolAddress((void**)&wkT, g_wkT);
    cudaGetSymbolAddress((void**)&wvT, g_wvT);
    cudaGetSymbolAddress((void**)&woT, g_woT);
    cudaGetSymbolAddress((void**)&w1T, g_w1T);
    cudaGetSymbolAddress((void**)&w2T, g_w2T);

    dim3 tb(32, 8);
    transpose_kernel<<<dim3(DD/32,   DD/32),   tb>>>(wq, wqT, DD,   DD);
    transpose_kernel<<<dim3(DD/32,   DD/32),   tb>>>(wk, wkT, DD,   DD);
    transpose_kernel<<<dim3(DD/32,   DD/32),   tb>>>(wv, wvT, DD,   DD);
    transpose_kernel<<<dim3(DD/32,   DD/32),   tb>>>(wo, woT, DD,   DD);
    transpose_kernel<<<dim3(DFFN/32, DD/32),   tb>>>(w1, w1T, DD,   DFFN);
    transpose_kernel<<<dim3(DD/32,   DFFN/32), tb>>>(w2, w2T, DFFN, DD);

    // 1) LN1 -> half
    ln_kernel<<<NTOK, 256>>>(x, xn, g1, be1);

    // 2) Q, K projections (half out); V stored transposed [b, d, s] (half)
    run_hgemm(xn, wqT, nullptr, q,  bq, nullptr, NTOK, DD, DD, DD, DD, DD, 0, 0, 1);
    run_hgemm(xn, wkT, nullptr, k,  bk, nullptr, NTOK, DD, DD, DD, DD, DD, 0, 0, 1);
    run_hgemm(xn, wvT, nullptr, vT, bv, nullptr, NTOK, DD, DD, DD, DD, DD, 0, 1, 1);

    // 3) fused attention: QK^T/8 -> mask(-1) -> softmax -> @V  (half in/out)
    {
        cudaFuncSetAttribute(flash_kernel, cudaFuncAttributeMaxDynamicSharedMemorySize,
                             FLASH_SMEM);
        dim3 grid(SS/128, BB*HH);
        flash_kernel<<<grid, 256, FLASH_SMEM>>>(q, k, vT, msk, ctx);
    }

    // 4) x1 = x + ctx @ wo + bo (float out)
    run_hgemm(ctx, woT, x1, nullptr, bo, x, NTOK, DD, DD, DD, DD, DD, 0, 0, 0);

    // 5) LN2 -> half
    ln_kernel<<<NTOK, 256>>>(x1, xn, g2, be2);

    // 6) h = relu(xn @ w1 + b1) (half out)
    run_hgemm(xn, w1T, nullptr, hb, b1, nullptr, NTOK, DFFN, DD, DD, DD, DFFN, 1, 0, 1);

    // 7) out = x1 + h @ w2 + b2 (float out)
    run_hgemm(hb, w2T, out, nullptr, b2, x1, NTOK, DD, DFFN, DFFN, DFFN, DD, 0, 0, 0);
}

// round 17
// speedup vs baseline: 1.7307x; 1.0295x over previous
#include <cuda_runtime.h>
#include <cuda_fp16.h>
#include <cstdint>
#include <math.h>

#define BB   2
#define SS   2048
#define DD   1024
#define HH   16
#define DKK  64
#define DFFN 4096
#define NTOK (BB*SS)

// ---------------- persistent scratch (no runtime allocation) ----------------
__device__ __half g_xn [NTOK*DD];
__device__ __half g_q  [NTOK*DD];
__device__ __half g_k  [NTOK*DD];
__device__ __half g_vT [(size_t)BB*DD*SS];     // V transposed: [b, d, s]
__device__ __half g_ctx[NTOK*DD];
__device__ float  g_x1 [NTOK*DD];
__device__ __half g_h  [(size_t)NTOK*DFFN];
__device__ __half g_wqT[DD*DD];
__device__ __half g_wkT[DD*DD];
__device__ __half g_wvT[DD*DD];
__device__ __half g_woT[DD*DD];
__device__ __half g_w1T[(size_t)DFFN*DD];
__device__ __half g_w2T[(size_t)DD*DFFN];

// ---------------- helpers ----------------
__device__ __forceinline__ uint32_t smem_u32(const void* p){
    uint32_t a;
    asm("{ .reg .u64 t; cvta.to.shared.u64 t, %1; cvt.u32.u64 %0, t; }" : "=r"(a) : "l"(p));
    return a;
}
__device__ __forceinline__ void cp16(uint32_t dst, const void* src){
    asm volatile("cp.async.cg.shared.global [%0], [%1], 16;"
                 :: "r"(dst), "l"(__cvta_generic_to_global(src)) : "memory");
}
__device__ __forceinline__ void mma16(float* acc, const uint32_t* af, uint32_t b0, uint32_t b1){
    asm volatile(
        "mma.sync.aligned.m16n8k16.row.col.f32.f16.f16.f32 "
        "{%0,%1,%2,%3}, {%4,%5,%6,%7}, {%8,%9}, {%0,%1,%2,%3};"
        : "+f"(acc[0]), "+f"(acc[1]), "+f"(acc[2]), "+f"(acc[3])
        : "r"(af[0]), "r"(af[1]), "r"(af[2]), "r"(af[3]), "r"(b0), "r"(b1));
}
__device__ __forceinline__ void ldsm4(uint32_t* r, uint32_t addr){
    asm volatile("ldmatrix.sync.aligned.m8n8.x4.shared.b16 {%0,%1,%2,%3}, [%4];"
        : "=r"(r[0]), "=r"(r[1]), "=r"(r[2]), "=r"(r[3]) : "r"(addr));
}

// ---------------- LayerNorm (ddof=1, /(std+eps)); output half ----------------
__global__ __launch_bounds__(256) void ln_kernel(
    const float* __restrict__ x, __half* __restrict__ out,
    const float* __restrict__ g, const float* __restrict__ b)
{
    __shared__ float red[256];
    int row = blockIdx.x;
    int tid = threadIdx.x;
    const float* xr = x + (size_t)row * DD;

    float v[4]; float s = 0.f;
#pragma unroll
    for (int i = 0; i < 4; i++) { v[i] = xr[tid + i*256]; s += v[i]; }
    red[tid] = s; __syncthreads();
    for (int o = 128; o > 0; o >>= 1) { if (tid < o) red[tid] += red[tid+o]; __syncthreads(); }
    float mean = red[0] / (float)DD;
    __syncthreads();

    float vs = 0.f;
#pragma unroll
    for (int i = 0; i < 4; i++) { float d = v[i] - mean; vs += d*d; }
    red[tid] = vs; __syncthreads();
    for (int o = 128; o > 0; o >>= 1) { if (tid < o) red[tid] += red[tid+o]; __syncthreads(); }
    float var = red[0] / (float)(DD - 1);
    float inv = 1.f / (sqrtf(var) + 1e-6f);
    float g0 = g[0], b0 = b[0];
    __half* orow = out + (size_t)row * DD;
#pragma unroll
    for (int i = 0; i < 4; i++)
        orow[tid + i*256] = __float2half(g0 * (v[i] - mean) * inv + b0);
}

// ---------------- weight transpose: float in -> half out [C][R] ----------------
__global__ __launch_bounds__(256) void transpose_kernel(
    const float* __restrict__ in, __half* __restrict__ out, int R, int Cc)
{
    __shared__ float t[32][33];
    int c0 = blockIdx.x * 32, r0 = blockIdx.y * 32;
    int x = threadIdx.x, y = threadIdx.y;      // block (32, 8)
#pragma unroll
    for (int i = y; i < 32; i += 8) t[i][x] = in[(size_t)(r0 + i) * Cc + c0 + x];
    __syncthreads();
#pragma unroll
    for (int i = y; i < 32; i += 8) out[(size_t)(c0 + i) * R + r0 + x] = __float2half(t[x][i]);
}

// ============================================================
// Fused flash attention (fp16 mma.sync m16n8k16), per CTA: 128 query rows, one (b,h).
// K-tiles of 128 keys; online softmax in f32; scores=(q.k)/8; mask==0 -> -1.0.
// smem u32 layout: sQ [128][36], sK [128][36], sV [64][68], sP [128][68], sM[128]
// (identical to the 720us-measured version)
// ============================================================
static constexpr int FQ = 0;
static constexpr int FK = 128*36;
static constexpr int FV = FK + 128*36;          // 9216
static constexpr int FP = FV + 64*68;           // 13568
static constexpr int FM = FP + 128*68;          // 22272
static constexpr int FLASH_SMEM = (FM + 128) * 4;   // 89600 B

__global__ __launch_bounds__(256)
void flash_kernel(const __half* __restrict__ q, const __half* __restrict__ k,
                  const __half* __restrict__ vT, const int* __restrict__ msk,
                  __half* __restrict__ ctx)
{
    extern __shared__ uint32_t sm32[];
    int* sM = (int*)(sm32 + FM);

    const int tid = threadIdx.x;
    const int z  = blockIdx.y, bz = z >> 4, hz = z & 15;
    const int s0 = blockIdx.x * 128;
    const int warp = tid >> 5, lane = tid & 31;
    const int g = lane >> 2, qd = lane & 3;
    const int rowA = warp * 16;

    const __half* qb = q  + ((size_t)(bz*SS + s0))*DD + hz*64;
    const __half* kb = k  + ((size_t)bz*SS)*DD + hz*64;
    const __half* vb = vT + (size_t)bz*DD*SS + (size_t)hz*64*SS;

    const uint32_t base = smem_u32(sm32);

    // Q tile (once): 128 rows x 64 halves (128B) = 8 chunks/row
#pragma unroll
    for (int p = 0; p < 4; p++){
        int slot = tid + p*256;
        int r = slot >> 3, qq = slot & 7;
        cp16(base + (uint32_t)(FQ + r*36 + qq*4)*4, qb + (size_t)r*DD + qq*8);
    }
    asm volatile("cp.async.commit_group;" ::: "memory");

    float m0 = -INFINITY, m1 = -INFINITY, l0 = 0.f, l1 = 0.f;
    float o[8][4];
#pragma unroll
    for (int nt = 0; nt < 8; nt++)
#pragma unroll
        for (int e = 0; e < 4; e++) o[nt][e] = 0.f;

    for (int kt = 0; kt < 16; kt++){
        __syncthreads();                       // previous tile fully consumed
        // K tile: [key 128][dk 64 halves]
#pragma unroll
        for (int p = 0; p < 4; p++){
            int slot = tid + p*256;
            int r = slot >> 3, qq = slot & 7;
            cp16(base + (uint32_t)(FK + r*36 + qq*4)*4,
                 kb + (size_t)(kt*128 + r)*DD + qq*8);
        }
        // V tile from vT: [dk 64][key 128 halves] (256B rows = 16 chunks)
#pragma unroll
        for (int p = 0; p < 4; p++){
            int slot = tid + p*256;
            int r = slot >> 4, qq = slot & 15;
            cp16(base + (uint32_t)(FV + r*68 + qq*4)*4,
                 vb + (size_t)r*SS + kt*128 + qq*8);
        }
        asm volatile("cp.async.commit_group;" ::: "memory");
        if (tid < 128) sM[tid] = msk[bz*SS + kt*128 + tid];
        asm volatile("cp.async.wait_group 0;" ::: "memory");
        __syncthreads();

        // ---- scores: 16 rows x 128 keys per warp, dk=64 -> 4 k16 chunks ----
        float s[16][4];
#pragma unroll
        for (int nt = 0; nt < 16; nt++)
#pragma unroll
            for (int e = 0; e < 4; e++) s[nt][e] = 0.f;

#pragma unroll
        for (int ks = 0; ks < 32; ks += 8){    // u32 offset per k16 chunk
            uint32_t af[4];
            af[0] = sm32[FQ + (rowA + g    )*36 + ks + qd];
            af[1] = sm32[FQ + (rowA + g + 8)*36 + ks + qd];
            af[2] = sm32[FQ + (rowA + g    )*36 + ks + qd + 4];
            af[3] = sm32[FQ + (rowA + g + 8)*36 + ks + qd + 4];
#pragma unroll
            for (int nt = 0; nt < 16; nt++){
                uint32_t b0 = sm32[FK + (nt*8 + g)*36 + ks + qd];
                uint32_t b1 = sm32[FK + (nt*8 + g)*36 + ks + qd + 4];
                mma16(s[nt], af, b0, b1);
            }
        }

        // ---- scale + mask + tile max ----
        float tm0 = -INFINITY, tm1 = -INFINITY;
#pragma unroll
        for (int nt = 0; nt < 16; nt++){
            int mc0 = sM[nt*8 + 2*qd], mc1 = sM[nt*8 + 2*qd + 1];
            s[nt][0] = mc0 ? s[nt][0] * 0.125f : -1.0f;
            s[nt][1] = mc1 ? s[nt][1] * 0.125f : -1.0f;
            s[nt][2] = mc0 ? s[nt][2] * 0.125f : -1.0f;
            s[nt][3] = mc1 ? s[nt][3] * 0.125f : -1.0f;
            tm0 = fmaxf(tm0, fmaxf(s[nt][0], s[nt][1]));
            tm1 = fmaxf(tm1, fmaxf(s[nt][2], s[nt][3]));
        }
        tm0 = fmaxf(tm0, __shfl_xor_sync(0xffffffffu, tm0, 1));
        tm0 = fmaxf(tm0, __shfl_xor_sync(0xffffffffu, tm0, 2));
        tm1 = fmaxf(tm1, __shfl_xor_sync(0xffffffffu, tm1, 1));
        tm1 = fmaxf(tm1, __shfl_xor_sync(0xffffffffu, tm1, 2));

        float mn0 = fmaxf(m0, tm0), mn1 = fmaxf(m1, tm1);
        float a0 = __expf(m0 - mn0), a1 = __expf(m1 - mn1);

        // ---- exp, row sums, write P (half2) to smem ----
        float ts0 = 0.f, ts1 = 0.f;
        uint32_t pr0 = FP + (rowA + g    )*68 + qd;
        uint32_t pr1 = FP + (rowA + g + 8)*68 + qd;
#pragma unroll
        for (int nt = 0; nt < 16; nt++){
            float p0 = __expf(s[nt][0] - mn0), p1 = __expf(s[nt][1] - mn0);
            float p2 = __expf(s[nt][2] - mn1), p3 = __expf(s[nt][3] - mn1);
            ts0 += p0 + p1; ts1 += p2 + p3;
            *reinterpret_cast<__half2*>(&sm32[pr0 + nt*4]) = __floats2half2_rn(p0, p1);
            *reinterpret_cast<__half2*>(&sm32[pr1 + nt*4]) = __floats2half2_rn(p2, p3);
        }
        ts0 += __shfl_xor_sync(0xffffffffu, ts0, 1);
        ts0 += __shfl_xor_sync(0xffffffffu, ts0, 2);
        ts1 += __shfl_xor_sync(0xffffffffu, ts1, 1);
        ts1 += __shfl_xor_sync(0xffffffffu, ts1, 2);

        l0 = l0 * a0 + ts0;  l1 = l1 * a1 + ts1;
        m0 = mn0;  m1 = mn1;

#pragma unroll
        for (int nt = 0; nt < 8; nt++){
            o[nt][0] *= a0; o[nt][1] *= a0;
            o[nt][2] *= a1; o[nt][3] *= a1;
        }
        __syncwarp();

        // ---- P @ V : 128 keys -> 8 k16 chunks ----
#pragma unroll
        for (int kk = 0; kk < 64; kk += 8){    // u32 offset
            uint32_t af[4];
            af[0] = sm32[FP + (rowA + g    )*68 + kk + qd];
            af[1] = sm32[FP + (rowA + g + 8)*68 + kk + qd];
            af[2] = sm32[FP + (rowA + g    )*68 + kk + qd + 4];
            af[3] = sm32[FP + (rowA + g + 8)*68 + kk + qd + 4];
#pragma unroll
            for (int nt = 0; nt < 8; nt++){
                uint32_t b0 = sm32[FV + (nt*8 + g)*68 + kk + qd];
                uint32_t b1 = sm32[FV + (nt*8 + g)*68 + kk + qd + 4];
                mma16(o[nt], af, b0, b1);
            }
        }
    }

    // ---- epilogue: normalize, write ctx [B,S,H,DK] as half ----
    float i0 = 1.f / l0, i1 = 1.f / l1;
    size_t r0i = ((size_t)(bz*SS + s0 + rowA + g    ))*DD + hz*64;
    size_t r1i = ((size_t)(bz*SS + s0 + rowA + g + 8))*DD + hz*64;
#pragma unroll
    for (int nt = 0; nt < 8; nt++){
        int c = nt*8 + 2*qd;
        *reinterpret_cast<__half2*>(&ctx[r0i + c]) = __floats2half2_rn(o[nt][0]*i0, o[nt][1]*i0);
        *reinterpret_cast<__half2*>(&ctx[r1i + c]) = __floats2half2_rn(o[nt][2]*i1, o[nt][3]*i1);
    }
}

// ============================================================
// fp16 mma GEMM (ldmatrix fragments): C[128 x 128] per CTA = A @ Bt^T
// A: [M,K] half row-major. Bt: [N,K] half row-major. K % 64 == 0.
// Stage = 64 halves of K; double-buffered cp.async; warp tile 64x32.
// Only change vs the 720us version: fragment loads via ldmatrix.x4.
// ============================================================
static constexpr int HG_ASZ = 128 * 36;     // u32 per stage tile (A and B identical)
static constexpr int HG_SMEM = 4 * HG_ASZ * 4;   // 73728 B

__global__ __launch_bounds__(256)
void hgemm(const __half* __restrict__ A, const __half* __restrict__ Bt,
           float* __restrict__ Cf, __half* __restrict__ Ch,
           const float* __restrict__ bias, const float* __restrict__ resid,
           int K, int lda, int ldb, int ldc,
           int relu, int storeT, int outHalf)
{
    extern __shared__ uint32_t sm32[];
    uint32_t* A0 = sm32;
    uint32_t* B0 = sm32 + 2 * HG_ASZ;

    const int tid = threadIdx.x;
    const int rowStart = blockIdx.y * 128;
    const int colStart = blockIdx.x * 128;

    const uint32_t aBase = smem_u32(A0), bBase = smem_u32(B0);

    auto loadA = [&](int buf, int k0){
        uint32_t dst = aBase + (uint32_t)buf * (HG_ASZ * 4);
#pragma unroll
        for (int p = 0; p < 4; p++){
            int slot = tid + p * 256;
            int r = slot >> 3, qq = slot & 7;
            cp16(dst + (uint32_t)(r * 36 + qq * 4) * 4,
                 A + (size_t)(rowStart + r) * lda + k0 + qq * 8);
        }
    };
    auto loadB = [&](int buf, int k0){
        uint32_t dst = bBase + (uint32_t)buf * (HG_ASZ * 4);
#pragma unroll
        for (int p = 0; p < 4; p++){
            int slot = tid + p * 256;
            int r = slot >> 3, qq = slot & 7;
            cp16(dst + (uint32_t)(r * 36 + qq * 4) * 4,
                 Bt + (size_t)(colStart + r) * ldb + k0 + qq * 8);
        }
    };

    const int warp = tid >> 5, lane = tid & 31;
    const int g = lane >> 2, qd = lane & 3;
    const int wy = warp >> 2, wx = warp & 3;
    const int m0 = wy * 64, n0 = wx * 32;

    // ldmatrix per-thread address components
    const int aRowOff = ((lane>>3)&1)*8 + (lane&7);   // matrices: {m0-7,k0},{m8-15,k0},{m0-7,k8},{m8-15,k8}
    const int aKOff   = (lane>>4)*4;
    const int bRowOff = ((lane>>4)&1)*8 + (lane&7);   // matrices: {n0-7,k0},{n0-7,k8},{n8-15,k0},{n8-15,k8}
    const int bKOff   = ((lane>>3)&1)*4;

    float acc[4][4][4];
#pragma unroll
    for (int mt = 0; mt < 4; mt++)
#pragma unroll
        for (int nt = 0; nt < 4; nt++)
#pragma unroll
            for (int e = 0; e < 4; e++) acc[mt][nt][e] = 0.f;

    const int nk = K >> 6;                     // 64 halves per stage
    loadA(0, 0); loadB(0, 0);
    asm volatile("cp.async.commit_group;" ::: "memory");

    for (int s = 0; s < nk; s++){
        if (s + 1 < nk){ loadA((s + 1) & 1, (s + 1) * 64); loadB((s + 1) & 1, (s + 1) * 64); }
        asm volatile("cp.async.commit_group;" ::: "memory");
        asm volatile("cp.async.wait_group 1;" ::: "memory");
        __syncthreads();

        const uint32_t aB = aBase + (uint32_t)((s & 1) * HG_ASZ) * 4;
        const uint32_t bB = bBase + (uint32_t)((s & 1) * HG_ASZ) * 4;
#pragma unroll
        for (int ks = 0; ks < 32; ks += 8){    // 4 chunks of k16 (u32 offsets)
            uint32_t af[4][4], bf[4][2];
#pragma unroll
            for (int mt = 0; mt < 4; mt++)
                ldsm4(af[mt], aB + (uint32_t)((m0 + mt*16 + aRowOff)*36 + ks + aKOff)*4);
#pragma unroll
            for (int p = 0; p < 2; p++){
                uint32_t r[4];
                ldsm4(r, bB + (uint32_t)((n0 + p*16 + bRowOff)*36 + ks + bKOff)*4);
                bf[2*p][0]   = r[0]; bf[2*p][1]   = r[1];
                bf[2*p+1][0] = r[2]; bf[2*p+1][1] = r[3];
            }
#pragma unroll
            for (int mt = 0; mt < 4; mt++)
#pragma unroll
                for (int nt = 0; nt < 4; nt++)
                    mma16(acc[mt][nt], af[mt], bf[nt][0], bf[nt][1]);
        }
        __syncthreads();
    }

    // ---------------- epilogue ----------------
#pragma unroll
    for (int mt = 0; mt < 4; mt++)
#pragma unroll
        for (int nt = 0; nt < 4; nt++)
#pragma unroll
            for (int e = 0; e < 4; e++){
                int r = rowStart + m0 + mt * 16 + g + ((e >= 2) ? 8 : 0);
                int c = colStart + n0 + nt * 8 + qd * 2 + (e & 1);
                float v = acc[mt][nt][e];
                if (bias)  v += bias[c];
                if (resid) v += resid[(size_t)r * ldc + c];
                if (relu)  v = fmaxf(v, 0.f);
                if (storeT) {
                    int bb = r >> 11;          // r / SS
                    int si = r & (SS - 1);
                    Ch[((size_t)bb * DD + c) * SS + si] = __float2half(v);
                } else if (outHalf) {
                    Ch[(size_t)r * ldc + c] = __float2half(v);
                } else {
                    Cf[(size_t)r * ldc + c] = v;
                }
            }
}

// ---------------- host-side launcher ----------------
static void run_hgemm(const __half* A, const __half* Bt,
                      float* Cf, __half* Ch,
                      const float* bias, const float* resid,
                      int M, int N, int K, int lda, int ldb, int ldc,
                      int relu, int storeT, int outHalf)
{
    cudaFuncSetAttribute(hgemm, cudaFuncAttributeMaxDynamicSharedMemorySize, HG_SMEM);
    dim3 grid(N / 128, M / 128, 1);
    hgemm<<<grid, 256, HG_SMEM>>>(A, Bt, Cf, Ch, bias, resid,
                                  K, lda, ldb, ldc, relu, storeT, outHalf);
}

extern "C" void kernel_launch(void* const* d_in, const int* in_sizes, int n_in,
                              void* d_out, int out_size)
{
    const float* x   = (const float*)d_in[0];
    const int*   msk = (const int*)  d_in[1];
    const float* wq  = (const float*)d_in[2];
    const float* bq  = (const float*)d_in[3];
    const float* wk  = (const float*)d_in[4];
    const float* bk  = (const float*)d_in[5];
    const float* wv  = (const float*)d_in[6];
    const float* bv  = (const float*)d_in[7];
    const float* wo  = (const float*)d_in[8];
    const float* bo  = (const float*)d_in[9];
    const float* w1  = (const float*)d_in[10];
    const float* b1  = (const float*)d_in[11];
    const float* w2  = (const float*)d_in[12];
    const float* b2  = (const float*)d_in[13];
    const float* g1  = (const float*)d_in[14];
    const float* be1 = (const float*)d_in[15];
    const float* g2  = (const float*)d_in[16];
    const float* be2 = (const float*)d_in[17];
    float* out = (float*)d_out;

    __half *xn,*q,*k,*vT,*ctx,*hb,*wqT,*wkT,*wvT,*woT,*w1T,*w2T;
    float *x1;
    cudaGetSymbolAddress((void**)&xn,  g_xn);
    cudaGetSymbolAddress((void**)&q,   g_q);
    cudaGetSymbolAddress((void**)&k,   g_k);
    cudaGetSymbolAddress((void**)&vT,  g_vT);
    cudaGetSymbolAddress((void**)&ctx, g_ctx);
    cudaGetSymbolAddress((void**)&x1,  g_x1);
    cudaGetSymbolAddress((void**)&hb,  g_h);
    cudaGetSymbolAddress((void**)&wqT, g_wqT);
    cudaGetSymbolAddress((void**)&wkT, g_wkT);
    cudaGetSymbolAddress((void**)&wvT, g_wvT);
    cudaGetSymbolAddress((void**)&woT, g_woT);
    cudaGetSymbolAddress((void**)&w1T, g_w1T);
    cudaGetSymbolAddress((void**)&w2T, g_w2T);

    dim3 tb(32, 8);
    transpose_kernel<<<dim3(DD/32,   DD/32),   tb>>>(wq, wqT, DD,   DD);
    transpose_kernel<<<dim3(DD/32,   DD/32),   tb>>>(wk, wkT, DD,   DD);
    transpose_kernel<<<dim3(DD/32,   DD/32),   tb>>>(wv, wvT, DD,   DD);
    transpose_kernel<<<dim3(DD/32,   DD/32),   tb>>>(wo, woT, DD,   DD);
    transpose_kernel<<<dim3(DFFN/32, DD/32),   tb>>>(w1, w1T, DD,   DFFN);
    transpose_kernel<<<dim3(DD/32,   DFFN/32), tb>>>(w2, w2T, DFFN, DD);

    // 1) LN1 -> half
    ln_kernel<<<NTOK, 256>>>(x, xn, g1, be1);

    // 2) Q, K projections (half out); V stored transposed [b, d, s] (half)
    run_hgemm(xn, wqT, nullptr, q,  bq, nullptr, NTOK, DD, DD, DD, DD, DD, 0, 0, 1);
    run_hgemm(xn, wkT, nullptr, k,  bk, nullptr, NTOK, DD, DD, DD, DD, DD, 0, 0, 1);
    run_hgemm(xn, wvT, nullptr, vT, bv, nullptr, NTOK, DD, DD, DD, DD, DD, 0, 1, 1);

    // 3) fused attention: QK^T/8 -> mask(-1) -> softmax -> @V  (half in/out)
    {
        cudaFuncSetAttribute(flash_kernel, cudaFuncAttributeMaxDynamicSharedMemorySize,
                             FLASH_SMEM);
        dim3 grid(SS/128, BB*HH);
        flash_kernel<<<grid, 256, FLASH_SMEM>>>(q, k, vT, msk, ctx);
    }

    // 4) x1 = x + ctx @ wo + bo (float out)
    run_hgemm(ctx, woT, x1, nullptr, bo, x, NTOK, DD, DD, DD, DD, DD, 0, 0, 0);

    // 5) LN2 -> half
    ln_kernel<<<NTOK, 256>>>(x1, xn, g2, be2);

    // 6) h = relu(xn @ w1 + b1) (half out)
    run_hgemm(xn, w1T, nullptr, hb, b1, nullptr, NTOK, DFFN, DD, DD, DD, DFFN, 1, 0, 1);

    // 7) out = x1 + h @ w2 + b2 (float out)
    run_hgemm(hb, w2T, out, nullptr, b2, x1, NTOK, DD, DFFN, DFFN, DFFN, DD, 0, 0, 0);
}